// round 6
// baseline (speedup 1.0000x reference)
#include <cuda_runtime.h>
#include <cstddef>

// Problem dims
#define B_  32
#define NN_ 16
#define T_  256
#define D_  512
#define C_  512
#define M_  (B_ * T_)   // 8192 rows of v_mean

// ---------------- scratch (device globals: no allocation allowed) ----------
static __device__ float g_vmean[(size_t)M_ * D_];   // 16 MB
static __device__ float g_tn[(size_t)C_ * D_];      // 1 MB

// ---------------- helpers --------------------------------------------------
__device__ __forceinline__ bool is_split1(const int* sp) {
    int v = *sp;
    // accept int 1 (int32/low word of int64) or float 1.0f bit pattern
    return (v == 1) || (v == 0x3F800000);
}

__device__ __forceinline__ unsigned long long dup2(float x) {
    unsigned long long r;
    asm("mov.b64 %0, {%1, %1};" : "=l"(r) : "f"(x));
    return r;
}
__device__ __forceinline__ void fma2(unsigned long long& d,
                                     unsigned long long a,
                                     unsigned long long b) {
    asm("fma.rn.f32x2 %0, %1, %2, %0;" : "+l"(d) : "l"(a), "l"(b));
}
__device__ __forceinline__ float2 unpack2(unsigned long long v) {
    float2 r;
    asm("mov.b64 {%0, %1}, %2;" : "=f"(r.x), "=f"(r.y) : "l"(v));
    return r;
}

// ---------------- kernel 1: normalize t_feat (512 rows) --------------------
__global__ __launch_bounds__(128)
void tnorm_kernel(const float* __restrict__ t, const int* __restrict__ split) {
    __shared__ float red[4];
    int c = blockIdx.x;
    const float4* tp = reinterpret_cast<const float4*>(t) + (size_t)c * (D_ / 4);
    float4 x = tp[threadIdx.x];
    float ss = x.x * x.x + x.y * x.y + x.z * x.z + x.w * x.w;
    #pragma unroll
    for (int off = 16; off > 0; off >>= 1)
        ss += __shfl_xor_sync(0xFFFFFFFFu, ss, off);
    int warp = threadIdx.x >> 5;
    if ((threadIdx.x & 31) == 0) red[warp] = ss;
    __syncthreads();
    ss = red[0] + red[1] + red[2] + red[3];

    float s = 1.0f;
    if (is_split1(split)) {
        float nrm = sqrtf(ss);
        s = 1.0f / fmaxf(nrm, 1e-12f);
    }
    float4 y = make_float4(x.x * s, x.y * s, x.z * s, x.w * s);
    float4* op = reinterpret_cast<float4*>(g_tn) + (size_t)c * (D_ / 4);
    op[threadIdx.x] = y;
}

// ---------------- kernel 2: normalize-each-n + mean over n -----------------
// One block per (b,t) row. 16 warps: warp w normalizes v[b, w, t, :] in regs
// (warp-shuffle sumsq), writes scaled row into smem; then 512 threads reduce
// over n and write v_mean. Reads 256 MB once (HBM-bound phase).
__global__ __launch_bounds__(512)
void vmean_kernel(const float* __restrict__ v, const int* __restrict__ split) {
    __shared__ float sm[NN_ * D_];   // 32 KB
    int row  = blockIdx.x;           // b*256 + t
    int w    = threadIdx.x >> 5;     // n index
    int lane = threadIdx.x & 31;
    int bb = row >> 8;
    int tt = row & 255;

    const float4* vp = reinterpret_cast<const float4*>(v) +
                       ((size_t)((bb * NN_ + w) * T_ + tt)) * (D_ / 4);
    float4 x0 = vp[lane];
    float4 x1 = vp[lane + 32];
    float4 x2 = vp[lane + 64];
    float4 x3 = vp[lane + 96];

    float ss = x0.x * x0.x + x0.y * x0.y + x0.z * x0.z + x0.w * x0.w
             + x1.x * x1.x + x1.y * x1.y + x1.z * x1.z + x1.w * x1.w
             + x2.x * x2.x + x2.y * x2.y + x2.z * x2.z + x2.w * x2.w
             + x3.x * x3.x + x3.y * x3.y + x3.z * x3.z + x3.w * x3.w;
    #pragma unroll
    for (int off = 16; off > 0; off >>= 1)
        ss += __shfl_xor_sync(0xFFFFFFFFu, ss, off);

    float s = 1.0f;
    if (is_split1(split)) {
        float nrm = sqrtf(ss);
        s = 1.0f / fmaxf(nrm, 1e-12f);
    }

    float4* smp = reinterpret_cast<float4*>(sm + w * D_);
    smp[lane]      = make_float4(x0.x * s, x0.y * s, x0.z * s, x0.w * s);
    smp[lane + 32] = make_float4(x1.x * s, x1.y * s, x1.z * s, x1.w * s);
    smp[lane + 64] = make_float4(x2.x * s, x2.y * s, x2.z * s, x2.w * s);
    smp[lane + 96] = make_float4(x3.x * s, x3.y * s, x3.z * s, x3.w * s);
    __syncthreads();

    int i = threadIdx.x;  // 0..511 -> d index
    float acc = 0.0f;
    #pragma unroll
    for (int n = 0; n < NN_; n++) acc += sm[n * D_ + i];
    g_vmean[(size_t)row * D_ + i] = acc * (1.0f / 16.0f);
}

// ---------------- kernel 3: GEMM (fp32x2 packed FFMA) ----------------------
// C[b,c,t] = (1/tau) * sum_d vmean[b*256+t][d] * tn[c][d]
// M=8192 (b,t), N=512 (c), K=512. Tiles: BM=128, BN=64, BK=16; 256 threads,
// per-thread 8x4 outputs as 16 packed f32x2 accumulators. smem stored
// k-major (transposed STS) so compute reads are LDS.128 along m/n.
#define BM 128
#define BN 64
#define BK 16
#define SA_STRIDE 132   // BM + 4 pad: 2-way STS conflicts only, 16B-aligned reads
#define SB_STRIDE 68    // BN + 4 pad

__global__ __launch_bounds__(256, 3)
void gemm_kernel(float* __restrict__ out) {
    __shared__ float sA[BK * SA_STRIDE];
    __shared__ float sB[BK * SB_STRIDE];

    int tid = threadIdx.x;
    int tx = tid & 15;    // n direction (4 cols each)
    int ty = tid >> 4;    // m direction (8 rows each)
    int m0 = blockIdx.y * BM;
    int n0 = blockIdx.x * BN;

    // global load mapping (per tile): A = 512 float4 (2/thread), B = 256 (1/thread)
    int kc   = tid & 3;       // k-chunk (float4) within row
    int row0 = tid >> 2;      // 0..63
    const float4* A4 = reinterpret_cast<const float4*>(g_vmean);
    const float4* B4 = reinterpret_cast<const float4*>(g_tn);
    size_t aBase0 = (size_t)(m0 + row0)      * (D_ / 4) + kc;
    size_t aBase1 = (size_t)(m0 + row0 + 64) * (D_ / 4) + kc;
    size_t bBase  = (size_t)(n0 + row0)      * (D_ / 4) + kc;

    float4 rA0 = A4[aBase0];
    float4 rA1 = A4[aBase1];
    float4 rB  = B4[bBase];

    unsigned long long acc[8][2];
    #pragma unroll
    for (int i = 0; i < 8; i++) { acc[i][0] = 0ull; acc[i][1] = 0ull; }

    const int NTILES = D_ / BK;  // 32
    for (int kt = 0; kt < NTILES; kt++) {
        // transposed STS into k-major smem
        int kb = kc * 4;
        sA[(kb + 0) * SA_STRIDE + row0] = rA0.x;
        sA[(kb + 1) * SA_STRIDE + row0] = rA0.y;
        sA[(kb + 2) * SA_STRIDE + row0] = rA0.z;
        sA[(kb + 3) * SA_STRIDE + row0] = rA0.w;
        sA[(kb + 0) * SA_STRIDE + row0 + 64] = rA1.x;
        sA[(kb + 1) * SA_STRIDE + row0 + 64] = rA1.y;
        sA[(kb + 2) * SA_STRIDE + row0 + 64] = rA1.z;
        sA[(kb + 3) * SA_STRIDE + row0 + 64] = rA1.w;
        sB[(kb + 0) * SB_STRIDE + row0] = rB.x;
        sB[(kb + 1) * SB_STRIDE + row0] = rB.y;
        sB[(kb + 2) * SB_STRIDE + row0] = rB.z;
        sB[(kb + 3) * SB_STRIDE + row0] = rB.w;
        __syncthreads();

        if (kt + 1 < NTILES) {  // register prefetch of next tile (overlaps compute)
            size_t off = (size_t)(kt + 1) * 4;
            rA0 = A4[aBase0 + off];
            rA1 = A4[aBase1 + off];
            rB  = B4[bBase + off];
        }

        #pragma unroll
        for (int k = 0; k < BK; k++) {
            float4 a0 = *reinterpret_cast<const float4*>(sA + k * SA_STRIDE + ty * 8);
            float4 a1 = *reinterpret_cast<const float4*>(sA + k * SA_STRIDE + ty * 8 + 4);
            ulonglong2 bp = *reinterpret_cast<const ulonglong2*>(sB + k * SB_STRIDE + tx * 4);
            unsigned long long a2;
            a2 = dup2(a0.x); fma2(acc[0][0], a2, bp.x); fma2(acc[0][1], a2, bp.y);
            a2 = dup2(a0.y); fma2(acc[1][0], a2, bp.x); fma2(acc[1][1], a2, bp.y);
            a2 = dup2(a0.z); fma2(acc[2][0], a2, bp.x); fma2(acc[2][1], a2, bp.y);
            a2 = dup2(a0.w); fma2(acc[3][0], a2, bp.x); fma2(acc[3][1], a2, bp.y);
            a2 = dup2(a1.x); fma2(acc[4][0], a2, bp.x); fma2(acc[4][1], a2, bp.y);
            a2 = dup2(a1.y); fma2(acc[5][0], a2, bp.x); fma2(acc[5][1], a2, bp.y);
            a2 = dup2(a1.z); fma2(acc[6][0], a2, bp.x); fma2(acc[6][1], a2, bp.y);
            a2 = dup2(a1.w); fma2(acc[7][0], a2, bp.x); fma2(acc[7][1], a2, bp.y);
        }
        __syncthreads();
    }

    // epilogue: out[b][c][t], t contiguous -> vectorize stores along t
    int bb = m0 >> 8;              // BM=128 tile never crosses a b boundary
    int t0 = (m0 & 255) + ty * 8;
    const float s = 1.0f / 0.07f;  // 1/tau (same for both splits)

    #pragma unroll
    for (int j = 0; j < 4; j++) {
        float cv[8];
        #pragma unroll
        for (int i = 0; i < 8; i++) {
            float2 p = unpack2(acc[i][j >> 1]);
            cv[i] = (j & 1) ? p.y : p.x;
        }
        float* op = out + ((size_t)(bb * C_ + n0 + tx * 4 + j)) * T_ + t0;
        *reinterpret_cast<float4*>(op)     = make_float4(cv[0] * s, cv[1] * s, cv[2] * s, cv[3] * s);
        *reinterpret_cast<float4*>(op + 4) = make_float4(cv[4] * s, cv[5] * s, cv[6] * s, cv[7] * s);
    }
}

// ---------------- launch ---------------------------------------------------
extern "C" void kernel_launch(void* const* d_in, const int* in_sizes, int n_in,
                              void* d_out, int out_size) {
    // identify inputs by element count (defensive vs ordering)
    const float* v = nullptr;
    const float* t = nullptr;
    const int* split = nullptr;
    for (int i = 0; i < n_in; i++) {
        if (in_sizes[i] == B_ * NN_ * T_ * D_) v = (const float*)d_in[i];
        else if (in_sizes[i] == C_ * D_)       t = (const float*)d_in[i];
        else                                    split = (const int*)d_in[i];
    }
    float* out = (float*)d_out;

    tnorm_kernel<<<C_, 128>>>(t, split);
    vmean_kernel<<<M_, 512>>>(v, split);
    dim3 grid(C_ / BN, M_ / BM);   // (8, 64) = 512 CTAs
    gemm_kernel<<<grid, 256>>>(out);
}

// round 10
// speedup vs baseline: 1.3553x; 1.3553x over previous
#include <cuda_runtime.h>
#include <cuda_bf16.h>
#include <cstdint>
#include <cstddef>

// Problem dims
#define B_  32
#define NN_ 16
#define T_  256
#define D_  512
#define C_  512
#define M_  (B_ * T_)      // 8192 rows of v_mean

#define KT16 (D_ / 16)     // 32 k-tiles

// ---------------- scratch: operands pre-packed in HMMA fragment layout -----
// A frag (m16n8k16, row-major A): tile (mt, kt), lane 0..31 holds 8 bf16
//   (regs a0..a3 pairs) contiguously -> one LDG.128 per lane per tile.
//   index = (((mt*32 + kt)*32 + lane)*8 + idx)
// B frag (col-major B = t_feat[k][n] view): tile (nt, kt), lane holds 4 bf16
//   (regs b0,b1 pairs) -> one LDG.64.
//   index = (((nt*32 + kt)*32 + lane)*4 + idx)
static __device__ __align__(16) __nv_bfloat16 g_afh[(size_t)M_ * D_];
static __device__ __align__(16) __nv_bfloat16 g_afl[(size_t)M_ * D_];
static __device__ __align__(16) __nv_bfloat16 g_bfh[(size_t)C_ * D_];
static __device__ __align__(16) __nv_bfloat16 g_bfl[(size_t)C_ * D_];

// ---------------- helpers --------------------------------------------------
__device__ __forceinline__ bool is_split1(const int* sp) {
    int v = *sp;
    return (v == 1) || (v == 0x3F800000);
}

__device__ __forceinline__ void split_bf16(float a, __nv_bfloat16& hi, __nv_bfloat16& lo) {
    hi = __float2bfloat16(a);
    lo = __float2bfloat16(a - __bfloat162float(hi));
}

#define MMA16816(C, A, B)                                                    \
    asm volatile(                                                            \
        "mma.sync.aligned.m16n8k16.row.col.f32.bf16.bf16.f32 "               \
        "{%0,%1,%2,%3}, {%4,%5,%6,%7}, {%8,%9}, {%0,%1,%2,%3};"              \
        : "+f"((C)[0]), "+f"((C)[1]), "+f"((C)[2]), "+f"((C)[3])             \
        : "r"((A).x), "r"((A).y), "r"((A).z), "r"((A).w),                    \
          "r"((B).x), "r"((B).y))

// ---------------- kernel 1: normalize t_feat -> B fragments ----------------
__global__ __launch_bounds__(128)
void tnorm_kernel(const float* __restrict__ t, const int* __restrict__ split) {
    __shared__ float red[4];
    int c = blockIdx.x;
    const float4* tp = reinterpret_cast<const float4*>(t) + (size_t)c * (D_ / 4);
    float4 x = tp[threadIdx.x];
    float ss = x.x * x.x + x.y * x.y + x.z * x.z + x.w * x.w;
    #pragma unroll
    for (int off = 16; off > 0; off >>= 1)
        ss += __shfl_xor_sync(0xFFFFFFFFu, ss, off);
    int warp = threadIdx.x >> 5;
    if ((threadIdx.x & 31) == 0) red[warp] = ss;
    __syncthreads();
    ss = red[0] + red[1] + red[2] + red[3];

    float s = 1.0f;
    if (is_split1(split)) s = 1.0f / fmaxf(sqrtf(ss), 1e-12f);

    int d0 = threadIdx.x * 4;
    float v[4] = { x.x * s, x.y * s, x.z * s, x.w * s };
    int g = c & 7;
    size_t ntbase = ((size_t)(c >> 3) * KT16) * 32;   // nt*32 tiles, *32 lanes
    #pragma unroll
    for (int j = 0; j < 4; j++) {
        int d = d0 + j;
        int kk = d & 15;
        int lane = (g << 2) | ((kk & 7) >> 1);
        int idx  = (kk & 1) | ((kk >> 3) << 1);
        size_t off = ((ntbase + (size_t)(d >> 4) * 32 + lane) << 2) + idx;
        __nv_bfloat16 hi, lo;
        split_bf16(v[j], hi, lo);
        g_bfh[off] = hi;
        g_bfl[off] = lo;
    }
}

// ---------------- kernel 2: normalize-each-n + mean -> A fragments ---------
// One block per (b,t) row; 16 warps each normalize one n-row (warp-shuffle
// sumsq), reduce over n in smem, emit hi/lo bf16 into fragment layout.
__global__ __launch_bounds__(512)
void vmean_kernel(const float* __restrict__ v, const int* __restrict__ split) {
    __shared__ float sm[NN_ * D_];   // 32 KB
    int row  = blockIdx.x;           // b*256 + t
    int w    = threadIdx.x >> 5;     // n index
    int lane = threadIdx.x & 31;
    int bb = row >> 8;
    int tt = row & 255;

    const float4* vp = reinterpret_cast<const float4*>(v) +
                       ((size_t)((bb * NN_ + w) * T_ + tt)) * (D_ / 4);
    float4 x0 = vp[lane];
    float4 x1 = vp[lane + 32];
    float4 x2 = vp[lane + 64];
    float4 x3 = vp[lane + 96];

    float ss = x0.x * x0.x + x0.y * x0.y + x0.z * x0.z + x0.w * x0.w
             + x1.x * x1.x + x1.y * x1.y + x1.z * x1.z + x1.w * x1.w
             + x2.x * x2.x + x2.y * x2.y + x2.z * x2.z + x2.w * x2.w
             + x3.x * x3.x + x3.y * x3.y + x3.z * x3.z + x3.w * x3.w;
    #pragma unroll
    for (int off = 16; off > 0; off >>= 1)
        ss += __shfl_xor_sync(0xFFFFFFFFu, ss, off);

    float s = 1.0f;
    if (is_split1(split)) s = 1.0f / fmaxf(sqrtf(ss), 1e-12f);

    float4* smp = reinterpret_cast<float4*>(sm + w * D_);
    smp[lane]      = make_float4(x0.x * s, x0.y * s, x0.z * s, x0.w * s);
    smp[lane + 32] = make_float4(x1.x * s, x1.y * s, x1.z * s, x1.w * s);
    smp[lane + 64] = make_float4(x2.x * s, x2.y * s, x2.z * s, x2.w * s);
    smp[lane + 96] = make_float4(x3.x * s, x3.y * s, x3.z * s, x3.w * s);
    __syncthreads();

    int d = threadIdx.x;             // 0..511
    float acc = 0.0f;
    #pragma unroll
    for (int n = 0; n < NN_; n++) acc += sm[n * D_ + d];
    float a = acc * (1.0f / 16.0f);

    // fragment-layout store
    int r = row & 15, cc = d & 15;
    int fl  = ((r & 7) << 2) | ((cc & 7) >> 1);
    int idx = (cc & 1) | ((r >> 3) << 1) | ((cc >> 3) << 2);
    size_t off = ((((size_t)(row >> 4) * KT16 + (d >> 4)) * 32 + fl) << 3) + idx;
    __nv_bfloat16 hi, lo;
    split_bf16(a, hi, lo);
    g_afh[off] = hi;
    g_afl[off] = lo;
}

// ---------------- kernel 3: bf16-split mma.sync GEMM -----------------------
// D[m, c] = sum_d A[m,d]*B[c,d]; out[b][c][t] = D/tau, m = b*256+t.
// CTA tile 128x128 (16 warps, warp tile 32x32: 2 m-tiles x 4 n-tiles).
// 3 HMMAs per (tile, k16): hi*hi + hi*lo + lo*hi. Fragments LDG'd directly
// from the pre-packed arrays (L2-resident); register ping-pong buffering.
__global__ __launch_bounds__(512)
void gemm_mma_kernel(float* __restrict__ out) {
    int tid = threadIdx.x;
    int w = tid >> 5, lane = tid & 31;
    int wm = w >> 2, wn = w & 3;
    int m0 = blockIdx.y * 128 + wm * 32;
    int n0 = blockIdx.x * 128 + wn * 32;

    // per-lane fragment pointers (uint4 = one A frag, uint2 = one B frag)
    const uint4* pAh = reinterpret_cast<const uint4*>(g_afh) + (size_t)(m0 >> 4) * (KT16 * 32) + lane;
    const uint4* pAl = reinterpret_cast<const uint4*>(g_afl) + (size_t)(m0 >> 4) * (KT16 * 32) + lane;
    const uint2* pBh = reinterpret_cast<const uint2*>(g_bfh) + (size_t)(n0 >> 3) * (KT16 * 32) + lane;
    const uint2* pBl = reinterpret_cast<const uint2*>(g_bfl) + (size_t)(n0 >> 3) * (KT16 * 32) + lane;

    float acc[2][4][4];
    #pragma unroll
    for (int mi = 0; mi < 2; mi++)
        #pragma unroll
        for (int ni = 0; ni < 4; ni++)
            #pragma unroll
            for (int j = 0; j < 4; j++) acc[mi][ni][j] = 0.0f;

    uint4 Ah[2][2], Al[2][2];
    uint2 Bh[2][4], Bl[2][4];

    // preload k-tile 0 into buffer 0 (mtile stride = KT16*32 frags = 1024)
    #pragma unroll
    for (int mi = 0; mi < 2; mi++) {
        Ah[0][mi] = pAh[mi * (KT16 * 32)];
        Al[0][mi] = pAl[mi * (KT16 * 32)];
    }
    #pragma unroll
    for (int ni = 0; ni < 4; ni++) {
        Bh[0][ni] = pBh[ni * (KT16 * 32)];
        Bl[0][ni] = pBl[ni * (KT16 * 32)];
    }

    #pragma unroll
    for (int kt = 0; kt < KT16; kt++) {
        int cur = kt & 1, nxt = cur ^ 1;
        if (kt + 1 < KT16) {
            int ko = (kt + 1) * 32;
            #pragma unroll
            for (int mi = 0; mi < 2; mi++) {
                Ah[nxt][mi] = pAh[mi * (KT16 * 32) + ko];
                Al[nxt][mi] = pAl[mi * (KT16 * 32) + ko];
            }
            #pragma unroll
            for (int ni = 0; ni < 4; ni++) {
                Bh[nxt][ni] = pBh[ni * (KT16 * 32) + ko];
                Bl[nxt][ni] = pBl[ni * (KT16 * 32) + ko];
            }
        }
        #pragma unroll
        for (int mi = 0; mi < 2; mi++)
            #pragma unroll
            for (int ni = 0; ni < 4; ni++) {
                MMA16816(acc[mi][ni], Ah[cur][mi], Bh[cur][ni]);
                MMA16816(acc[mi][ni], Ah[cur][mi], Bl[cur][ni]);
                MMA16816(acc[mi][ni], Al[cur][mi], Bh[cur][ni]);
            }
    }

    // epilogue: out[b][c][t] (t contiguous, stride 256 per c)
    int b  = m0 >> 8;                      // CTA m-tile never crosses a b boundary
    int t  = (m0 & 255) + (lane >> 2);
    const float s = 1.0f / 0.07f;          // 1/tau (both splits)
    #pragma unroll
    for (int mi = 0; mi < 2; mi++) {
        #pragma unroll
        for (int ni = 0; ni < 4; ni++) {
            int c = n0 + ni * 8 + (lane & 3) * 2;
            float* p = out + (((size_t)b * C_ + c) << 8) + t + mi * 16;
            p[0]   = acc[mi][ni][0] * s;   // (t,   c)
            p[256] = acc[mi][ni][1] * s;   // (t,   c+1)
            p[8]   = acc[mi][ni][2] * s;   // (t+8, c)
            p[264] = acc[mi][ni][3] * s;   // (t+8, c+1)
        }
    }
}

// ---------------- launch ---------------------------------------------------
extern "C" void kernel_launch(void* const* d_in, const int* in_sizes, int n_in,
                              void* d_out, int out_size) {
    const float* v = nullptr;
    const float* t = nullptr;
    const int* split = nullptr;
    for (int i = 0; i < n_in; i++) {
        if (in_sizes[i] == B_ * NN_ * T_ * D_) v = (const float*)d_in[i];
        else if (in_sizes[i] == C_ * D_)       t = (const float*)d_in[i];
        else                                    split = (const int*)d_in[i];
    }
    float* out = (float*)d_out;

    tnorm_kernel<<<C_, 128>>>(t, split);
    vmean_kernel<<<M_, 512>>>(v, split);
    dim3 grid(C_ / 128, M_ / 128);   // (4, 64) = 256 CTAs
    gemm_mma_kernel<<<grid, 512>>>(out);
}